// round 11
// baseline (speedup 1.0000x reference)
#include <cuda_runtime.h>
#include <cuda_fp16.h>
#include <math.h>

// Problem constants (fixed-shape problem)
#define MAXN 50048
#define MAXE 1600000
#define HID 128
#define NH 8
#define HD 16
#define SCAN_BLK 256
#define GATHER_CHUNK 16

// ---------------- device scratch (no allocation allowed) ----------------
__device__ float  g_Q[MAXN * HID];        // fp32 (read once per node)
// Interleaved K/V fp16: per node 256 halves; group g (=dim/4) at offset
// g*8: [K0 K1 K2 K3 V0 V1 V2 V3]. One uint4 per lane per edge.
__device__ __half g_KV[MAXN * 2 * HID];
__device__ int g_cnt[MAXN];               // zero-init; re-zeroed in scan_final
__device__ int g_off[MAXN];
__device__ int g_cur[MAXN];
__device__ int g_esrc[MAXE];
__device__ int g_bsum[512];
__device__ int g_work;                    // work-stealing cursor (reset in scan_bsums)

// ---------------- QKV GEMM (tf32 tensor cores) ---------------------------
__device__ __forceinline__ float cvt_tf32f(float v)
{
    unsigned r;
    asm("cvt.rna.tf32.f32 %0, %1;" : "=r"(r) : "f"(v));
    return __uint_as_float(r);
}

__global__ __launch_bounds__(256) void qkv_gemm(
    const float* __restrict__ h,
    const float* __restrict__ wq, const float* __restrict__ bq,
    const float* __restrict__ wk, const float* __restrict__ bk,
    const float* __restrict__ wv, const float* __restrict__ bv,
    int n)
{
    const float* W; const float* bias;
    float* outf = 0;
    int kvOff = 0;            // 0 for K, 4 for V (within 8-half group)
    if (blockIdx.y == 0)      { W = wq; bias = bq; outf = g_Q; }
    else if (blockIdx.y == 1) { W = wk; bias = bk; kvOff = 0; }
    else                      { W = wv; bias = bv; kvOff = 4; }

    __shared__ float As[32][132];   // [k][m], tf32-rounded
    __shared__ float Bs[32][132];   // [k][n], tf32-rounded

    const int tid  = threadIdx.x;
    const int lane = tid & 31;
    const int wid  = tid >> 5;          // 0..7
    const int wm   = wid >> 2;          // 0..1 -> M offset wm*64
    const int wn   = wid & 3;           // 0..3 -> N offset wn*32
    const int g    = lane >> 2;         // groupID 0..7
    const int tg   = lane & 3;          // thread-in-group 0..3
    const int row0 = blockIdx.x * 128;

    float c[4][4][4];
#pragma unroll
    for (int mi = 0; mi < 4; mi++)
#pragma unroll
        for (int ni = 0; ni < 4; ni++)
#pragma unroll
            for (int r = 0; r < 4; r++) c[mi][ni][r] = 0.f;

    for (int kk = 0; kk < HID; kk += 32) {
        {
            int m    = tid >> 1;
            int base = (tid & 1) * 16;
            int row  = row0 + m;
#pragma unroll
            for (int i = 0; i < 4; i++) {
                float4 v = make_float4(0.f, 0.f, 0.f, 0.f);
                if (row < n)
                    v = *(const float4*)(h + (size_t)row * HID + kk + base + i * 4);
                As[base + i * 4 + 0][m] = cvt_tf32f(v.x);
                As[base + i * 4 + 1][m] = cvt_tf32f(v.y);
                As[base + i * 4 + 2][m] = cvt_tf32f(v.z);
                As[base + i * 4 + 3][m] = cvt_tf32f(v.w);
            }
        }
        {
            int k    = tid >> 3;
            int base = (tid & 7) * 16;
#pragma unroll
            for (int i = 0; i < 4; i++) {
                float4 v = *(const float4*)(W + (size_t)(kk + k) * 128 + base + i * 4);
                Bs[k][base + i * 4 + 0] = cvt_tf32f(v.x);
                Bs[k][base + i * 4 + 1] = cvt_tf32f(v.y);
                Bs[k][base + i * 4 + 2] = cvt_tf32f(v.z);
                Bs[k][base + i * 4 + 3] = cvt_tf32f(v.w);
            }
        }
        __syncthreads();

#pragma unroll
        for (int ks = 0; ks < 4; ks++) {
            const int k0 = ks * 8;
            unsigned a[4][4];
#pragma unroll
            for (int mi = 0; mi < 4; mi++) {
                int m0 = wm * 64 + mi * 16;
                a[mi][0] = __float_as_uint(As[k0 + tg    ][m0 + g    ]);
                a[mi][1] = __float_as_uint(As[k0 + tg    ][m0 + g + 8]);
                a[mi][2] = __float_as_uint(As[k0 + tg + 4][m0 + g    ]);
                a[mi][3] = __float_as_uint(As[k0 + tg + 4][m0 + g + 8]);
            }
            unsigned b[4][2];
#pragma unroll
            for (int ni = 0; ni < 4; ni++) {
                int n0 = wn * 32 + ni * 8;
                b[ni][0] = __float_as_uint(Bs[k0 + tg    ][n0 + g]);
                b[ni][1] = __float_as_uint(Bs[k0 + tg + 4][n0 + g]);
            }
#pragma unroll
            for (int mi = 0; mi < 4; mi++)
#pragma unroll
                for (int ni = 0; ni < 4; ni++) {
                    asm volatile(
                        "mma.sync.aligned.m16n8k8.row.col.f32.tf32.tf32.f32 "
                        "{%0,%1,%2,%3}, {%4,%5,%6,%7}, {%8,%9}, {%0,%1,%2,%3};"
                        : "+f"(c[mi][ni][0]), "+f"(c[mi][ni][1]),
                          "+f"(c[mi][ni][2]), "+f"(c[mi][ni][3])
                        : "r"(a[mi][0]), "r"(a[mi][1]), "r"(a[mi][2]), "r"(a[mi][3]),
                          "r"(b[ni][0]), "r"(b[ni][1]));
                }
        }
        __syncthreads();
    }

    // epilogue: add bias, store (c0,c1 -> row g; c2,c3 -> row g+8)
#pragma unroll
    for (int ni = 0; ni < 4; ni++) {
        int col = wn * 32 + ni * 8 + tg * 2;
        float bx = bias[col], by = bias[col + 1];
        int kvIdx = ((col >> 2) << 3) + (col & 3) + kvOff;
#pragma unroll
        for (int mi = 0; mi < 4; mi++) {
            int rowA = row0 + wm * 64 + mi * 16 + g;
            int rowB = rowA + 8;
            if (outf) {
                if (rowA < n) {
                    float2 o = make_float2(c[mi][ni][0] + bx, c[mi][ni][1] + by);
                    *(float2*)(outf + (size_t)rowA * 128 + col) = o;
                }
                if (rowB < n) {
                    float2 o = make_float2(c[mi][ni][2] + bx, c[mi][ni][3] + by);
                    *(float2*)(outf + (size_t)rowB * 128 + col) = o;
                }
            } else {
                if (rowA < n) {
                    __half2 o = __floats2half2_rn(c[mi][ni][0] + bx, c[mi][ni][1] + by);
                    *(__half2*)(g_KV + (size_t)rowA * 256 + kvIdx) = o;
                }
                if (rowB < n) {
                    __half2 o = __floats2half2_rn(c[mi][ni][2] + bx, c[mi][ni][3] + by);
                    *(__half2*)(g_KV + (size_t)rowB * 256 + kvIdx) = o;
                }
            }
        }
    }
}

// ---------------- CSR construction --------------------------------------
__global__ void hist_kernel(const int* __restrict__ dst, int E)
{
    int i = blockIdx.x * blockDim.x + threadIdx.x;
    if (i < E) atomicAdd(&g_cnt[dst[i]], 1);
}

__global__ __launch_bounds__(SCAN_BLK) void scan_partial(int n)
{
    __shared__ int sh[SCAN_BLK];
    int i = blockIdx.x * SCAN_BLK + threadIdx.x;
    int v = (i < n) ? g_cnt[i] : 0;
    sh[threadIdx.x] = v;
    __syncthreads();
    for (int off = SCAN_BLK / 2; off > 0; off >>= 1) {
        if (threadIdx.x < off) sh[threadIdx.x] += sh[threadIdx.x + off];
        __syncthreads();
    }
    if (threadIdx.x == 0) g_bsum[blockIdx.x] = sh[0];
}

// also resets the gather work cursor (ordered before gat_gather via stream)
__global__ __launch_bounds__(SCAN_BLK) void scan_bsums(int nb)
{
    __shared__ int sh[SCAN_BLK];
    int t = threadIdx.x;
    if (t == 0) g_work = 0;
    int v = (t < nb) ? g_bsum[t] : 0;
    sh[t] = v;
    __syncthreads();
    for (int off = 1; off < SCAN_BLK; off <<= 1) {
        int u = (t >= off) ? sh[t - off] : 0;
        __syncthreads();
        sh[t] += u;
        __syncthreads();
    }
    if (t < nb) g_bsum[t] = sh[t] - v;   // exclusive
}

// reads g_cnt, writes g_off/g_cur, re-zeroes g_cnt (deterministic replay).
__global__ __launch_bounds__(SCAN_BLK) void scan_final(int n)
{
    __shared__ int sh[SCAN_BLK];
    int i = blockIdx.x * SCAN_BLK + threadIdx.x;
    int t = threadIdx.x;
    int v = (i < n) ? g_cnt[i] : 0;
    sh[t] = v;
    __syncthreads();
    for (int off = 1; off < SCAN_BLK; off <<= 1) {
        int u = (t >= off) ? sh[t - off] : 0;
        __syncthreads();
        sh[t] += u;
        __syncthreads();
    }
    if (i < n) {
        int excl = sh[t] - v + g_bsum[blockIdx.x];
        g_off[i] = excl;
        g_cur[i] = excl;
        g_cnt[i] = 0;
    }
}

__global__ void scatter_kernel(const int* __restrict__ src,
                               const int* __restrict__ dst, int E)
{
    int i = blockIdx.x * blockDim.x + threadIdx.x;
    if (i < E) {
        int p = atomicAdd(&g_cur[dst[i]], 1);
        g_esrc[p] = src[i];
    }
}

// ---------------- gather: persistent, warp-level work stealing -----------
// Each warp grabs GATHER_CHUNK nodes at a time from a global cursor, so
// early-finishing warps steal more work (fixes Poisson-degree imbalance).
// Per-node computation is identical regardless of which warp runs it.
__global__ __launch_bounds__(256) void gat_gather(float* __restrict__ out, int n)
{
    const int lane = threadIdx.x & 31;
    const int t = lane * 4;

    for (;;) {
        int base = 0;
        if (lane == 0) base = atomicAdd(&g_work, GATHER_CHUNK);
        base = __shfl_sync(0xFFFFFFFFu, base, 0);
        if (base >= n) return;
        int lim = min(base + GATHER_CHUNK, n);

        for (int node = base; node < lim; node++) {
            const int start = g_off[node];
            const int end   = g_cur[node];

            const float4 q = *(const float4*)(g_Q + (size_t)node * 128 + t);

            float ax = 0.f, ay = 0.f, az = 0.f, aw = 0.f;
            float den = 0.f;

            int i = start;
            for (; i + 1 < end; i += 2) {
                int s0 = g_esrc[i];
                int s1 = g_esrc[i + 1];
                uint4 kv0 = *(const uint4*)(g_KV + (size_t)s0 * 256 + lane * 8);
                uint4 kv1 = *(const uint4*)(g_KV + (size_t)s1 * 256 + lane * 8);

                float2 k01 = __half22float2(*(__half2*)&kv0.x);
                float2 k23 = __half22float2(*(__half2*)&kv0.y);
                float p0 = q.x * k01.x + q.y * k01.y + q.z * k23.x + q.w * k23.y;
                float2 l01 = __half22float2(*(__half2*)&kv1.x);
                float2 l23 = __half22float2(*(__half2*)&kv1.y);
                float p1 = q.x * l01.x + q.y * l01.y + q.z * l23.x + q.w * l23.y;

                p0 += __shfl_xor_sync(0xFFFFFFFFu, p0, 1);
                p1 += __shfl_xor_sync(0xFFFFFFFFu, p1, 1);
                p0 += __shfl_xor_sync(0xFFFFFFFFu, p0, 2);
                p1 += __shfl_xor_sync(0xFFFFFFFFu, p1, 2);
                float e0 = __expf(p0 * 0.25f);
                float e1 = __expf(p1 * 0.25f);

                float2 v01 = __half22float2(*(__half2*)&kv0.z);
                float2 v23 = __half22float2(*(__half2*)&kv0.w);
                float2 w01 = __half22float2(*(__half2*)&kv1.z);
                float2 w23 = __half22float2(*(__half2*)&kv1.w);
                ax = fmaf(e0, v01.x, fmaf(e1, w01.x, ax));
                ay = fmaf(e0, v01.y, fmaf(e1, w01.y, ay));
                az = fmaf(e0, v23.x, fmaf(e1, w23.x, az));
                aw = fmaf(e0, v23.y, fmaf(e1, w23.y, aw));
                den += e0 + e1;
            }
            if (i < end) {
                int s = g_esrc[i];
                uint4 kv = *(const uint4*)(g_KV + (size_t)s * 256 + lane * 8);
                float2 k01 = __half22float2(*(__half2*)&kv.x);
                float2 k23 = __half22float2(*(__half2*)&kv.y);
                float p = q.x * k01.x + q.y * k01.y + q.z * k23.x + q.w * k23.y;
                p += __shfl_xor_sync(0xFFFFFFFFu, p, 1);
                p += __shfl_xor_sync(0xFFFFFFFFu, p, 2);
                float e = __expf(p * 0.25f);
                float2 v01 = __half22float2(*(__half2*)&kv.z);
                float2 v23 = __half22float2(*(__half2*)&kv.w);
                ax = fmaf(e, v01.x, ax);
                ay = fmaf(e, v01.y, ay);
                az = fmaf(e, v23.x, az);
                aw = fmaf(e, v23.y, aw);
                den += e;
            }

            float inv = 1.f / den;
            float4 o;
            o.x = ax * inv; o.y = ay * inv; o.z = az * inv; o.w = aw * inv;
            *(float4*)(out + (size_t)node * 128 + t) = o;
        }
    }
}

// ---------------- launch ------------------------------------------------
// Side stream + events: created lazily on FIRST call (uncaptured correctness
// run), not at static-init. Same work submitted every call -> deterministic.
struct ForkResources {
    cudaStream_t s1;
    cudaEvent_t evFork, evJoin;
    ForkResources() {
        cudaStreamCreateWithFlags(&s1, cudaStreamNonBlocking);
        cudaEventCreateWithFlags(&evFork, cudaEventDisableTiming);
        cudaEventCreateWithFlags(&evJoin, cudaEventDisableTiming);
    }
};

extern "C" void kernel_launch(void* const* d_in, const int* in_sizes, int n_in,
                              void* d_out, int out_size)
{
    static ForkResources fork;   // first call, after harness init

    const float* h  = (const float*)d_in[0];
    const float* wq = (const float*)d_in[1];
    const float* bq = (const float*)d_in[2];
    const float* wk = (const float*)d_in[3];
    const float* bk = (const float*)d_in[4];
    const float* wv = (const float*)d_in[5];
    const float* bv = (const float*)d_in[6];
    const int*  src = (const int*)d_in[7];
    const int*  dst = (const int*)d_in[8];

    const int n = in_sizes[0] / HID;
    const int E = in_sizes[7];
    const int nb = (n + SCAN_BLK - 1) / SCAN_BLK;

    float* out = (float*)d_out;

    // Fork: CSR build on side stream, GEMM on main stream. Join before gather.
    cudaEventRecord(fork.evFork, 0);
    cudaStreamWaitEvent(fork.s1, fork.evFork, 0);

    hist_kernel<<<(E + 255) / 256, 256, 0, fork.s1>>>(dst, E);
    scan_partial<<<nb, SCAN_BLK, 0, fork.s1>>>(n);
    scan_bsums<<<1, SCAN_BLK, 0, fork.s1>>>(nb);     // also resets g_work
    scan_final<<<nb, SCAN_BLK, 0, fork.s1>>>(n);
    scatter_kernel<<<(E + 255) / 256, 256, 0, fork.s1>>>(src, dst, E);
    cudaEventRecord(fork.evJoin, fork.s1);

    {
        dim3 grid((n + 127) / 128, 3);
        qkv_gemm<<<grid, 256>>>(h, wq, bq, wk, bk, wv, bv, n);
    }

    cudaStreamWaitEvent(0, fork.evJoin, 0);
    // persistent gather: ~4 blocks/SM on 148 SMs
    gat_gather<<<592, 256>>>(out, n);
}

// round 13
// speedup vs baseline: 1.3226x; 1.3226x over previous
#include <cuda_runtime.h>
#include <cuda_fp16.h>
#include <math.h>

// Problem constants (fixed-shape problem)
#define MAXN 50048
#define MAXE 1600000
#define HID 128
#define NH 8
#define HD 16
#define SCAN_BLK 256

// ---------------- device scratch (no allocation allowed) ----------------
__device__ float  g_Q[MAXN * HID];        // fp32 (read once per node)
// Interleaved K/V fp16: per node 256 halves; group g (=dim/4) at offset
// g*8: [K0 K1 K2 K3 V0 V1 V2 V3]. One uint4 per lane per edge.
__device__ __half g_KV[MAXN * 2 * HID];
__device__ int g_cnt[MAXN];               // zero-init; re-zeroed in scan_final
__device__ int g_off[MAXN];
__device__ int g_cur[MAXN];
__device__ int g_esrc[MAXE];
__device__ int g_bsum[512];

// ---------------- QKV GEMM (tf32 tensor cores) ---------------------------
__device__ __forceinline__ float cvt_tf32f(float v)
{
    unsigned r;
    asm("cvt.rna.tf32.f32 %0, %1;" : "=r"(r) : "f"(v));
    return __uint_as_float(r);
}

__global__ __launch_bounds__(256) void qkv_gemm(
    const float* __restrict__ h,
    const float* __restrict__ wq, const float* __restrict__ bq,
    const float* __restrict__ wk, const float* __restrict__ bk,
    const float* __restrict__ wv, const float* __restrict__ bv,
    int n)
{
    const float* W; const float* bias;
    float* outf = 0;
    int kvOff = 0;            // 0 for K, 4 for V (within 8-half group)
    if (blockIdx.y == 0)      { W = wq; bias = bq; outf = g_Q; }
    else if (blockIdx.y == 1) { W = wk; bias = bk; kvOff = 0; }
    else                      { W = wv; bias = bv; kvOff = 4; }

    __shared__ float As[32][132];   // [k][m], tf32-rounded
    __shared__ float Bs[32][132];   // [k][n], tf32-rounded

    const int tid  = threadIdx.x;
    const int lane = tid & 31;
    const int wid  = tid >> 5;          // 0..7
    const int wm   = wid >> 2;          // 0..1 -> M offset wm*64
    const int wn   = wid & 3;           // 0..3 -> N offset wn*32
    const int g    = lane >> 2;         // groupID 0..7
    const int tg   = lane & 3;          // thread-in-group 0..3
    const int row0 = blockIdx.x * 128;

    float c[4][4][4];
#pragma unroll
    for (int mi = 0; mi < 4; mi++)
#pragma unroll
        for (int ni = 0; ni < 4; ni++)
#pragma unroll
            for (int r = 0; r < 4; r++) c[mi][ni][r] = 0.f;

    for (int kk = 0; kk < HID; kk += 32) {
        {
            int m    = tid >> 1;
            int base = (tid & 1) * 16;
            int row  = row0 + m;
#pragma unroll
            for (int i = 0; i < 4; i++) {
                float4 v = make_float4(0.f, 0.f, 0.f, 0.f);
                if (row < n)
                    v = *(const float4*)(h + (size_t)row * HID + kk + base + i * 4);
                As[base + i * 4 + 0][m] = cvt_tf32f(v.x);
                As[base + i * 4 + 1][m] = cvt_tf32f(v.y);
                As[base + i * 4 + 2][m] = cvt_tf32f(v.z);
                As[base + i * 4 + 3][m] = cvt_tf32f(v.w);
            }
        }
        {
            int k    = tid >> 3;
            int base = (tid & 7) * 16;
#pragma unroll
            for (int i = 0; i < 4; i++) {
                float4 v = *(const float4*)(W + (size_t)(kk + k) * 128 + base + i * 4);
                Bs[k][base + i * 4 + 0] = cvt_tf32f(v.x);
                Bs[k][base + i * 4 + 1] = cvt_tf32f(v.y);
                Bs[k][base + i * 4 + 2] = cvt_tf32f(v.z);
                Bs[k][base + i * 4 + 3] = cvt_tf32f(v.w);
            }
        }
        __syncthreads();

#pragma unroll
        for (int ks = 0; ks < 4; ks++) {
            const int k0 = ks * 8;
            unsigned a[4][4];
#pragma unroll
            for (int mi = 0; mi < 4; mi++) {
                int m0 = wm * 64 + mi * 16;
                a[mi][0] = __float_as_uint(As[k0 + tg    ][m0 + g    ]);
                a[mi][1] = __float_as_uint(As[k0 + tg    ][m0 + g + 8]);
                a[mi][2] = __float_as_uint(As[k0 + tg + 4][m0 + g    ]);
                a[mi][3] = __float_as_uint(As[k0 + tg + 4][m0 + g + 8]);
            }
            unsigned b[4][2];
#pragma unroll
            for (int ni = 0; ni < 4; ni++) {
                int n0 = wn * 32 + ni * 8;
                b[ni][0] = __float_as_uint(Bs[k0 + tg    ][n0 + g]);
                b[ni][1] = __float_as_uint(Bs[k0 + tg + 4][n0 + g]);
            }
#pragma unroll
            for (int mi = 0; mi < 4; mi++)
#pragma unroll
                for (int ni = 0; ni < 4; ni++) {
                    asm volatile(
                        "mma.sync.aligned.m16n8k8.row.col.f32.tf32.tf32.f32 "
                        "{%0,%1,%2,%3}, {%4,%5,%6,%7}, {%8,%9}, {%0,%1,%2,%3};"
                        : "+f"(c[mi][ni][0]), "+f"(c[mi][ni][1]),
                          "+f"(c[mi][ni][2]), "+f"(c[mi][ni][3])
                        : "r"(a[mi][0]), "r"(a[mi][1]), "r"(a[mi][2]), "r"(a[mi][3]),
                          "r"(b[ni][0]), "r"(b[ni][1]));
                }
        }
        __syncthreads();
    }

    // epilogue: add bias, store (c0,c1 -> row g; c2,c3 -> row g+8)
#pragma unroll
    for (int ni = 0; ni < 4; ni++) {
        int col = wn * 32 + ni * 8 + tg * 2;
        float bx = bias[col], by = bias[col + 1];
        int kvIdx = ((col >> 2) << 3) + (col & 3) + kvOff;
#pragma unroll
        for (int mi = 0; mi < 4; mi++) {
            int rowA = row0 + wm * 64 + mi * 16 + g;
            int rowB = rowA + 8;
            if (outf) {
                if (rowA < n) {
                    float2 o = make_float2(c[mi][ni][0] + bx, c[mi][ni][1] + by);
                    *(float2*)(outf + (size_t)rowA * 128 + col) = o;
                }
                if (rowB < n) {
                    float2 o = make_float2(c[mi][ni][2] + bx, c[mi][ni][3] + by);
                    *(float2*)(outf + (size_t)rowB * 128 + col) = o;
                }
            } else {
                if (rowA < n) {
                    __half2 o = __floats2half2_rn(c[mi][ni][0] + bx, c[mi][ni][1] + by);
                    *(__half2*)(g_KV + (size_t)rowA * 256 + kvIdx) = o;
                }
                if (rowB < n) {
                    __half2 o = __floats2half2_rn(c[mi][ni][2] + bx, c[mi][ni][3] + by);
                    *(__half2*)(g_KV + (size_t)rowB * 256 + kvIdx) = o;
                }
            }
        }
    }
}

// ---------------- CSR construction --------------------------------------
__global__ void hist_kernel(const int* __restrict__ dst, int E)
{
    int i = blockIdx.x * blockDim.x + threadIdx.x;
    if (i < E) atomicAdd(&g_cnt[dst[i]], 1);
}

__global__ __launch_bounds__(SCAN_BLK) void scan_partial(int n)
{
    __shared__ int sh[SCAN_BLK];
    int i = blockIdx.x * SCAN_BLK + threadIdx.x;
    int v = (i < n) ? g_cnt[i] : 0;
    sh[threadIdx.x] = v;
    __syncthreads();
    for (int off = SCAN_BLK / 2; off > 0; off >>= 1) {
        if (threadIdx.x < off) sh[threadIdx.x] += sh[threadIdx.x + off];
        __syncthreads();
    }
    if (threadIdx.x == 0) g_bsum[blockIdx.x] = sh[0];
}

__global__ __launch_bounds__(SCAN_BLK) void scan_bsums(int nb)
{
    __shared__ int sh[SCAN_BLK];
    int t = threadIdx.x;
    int v = (t < nb) ? g_bsum[t] : 0;
    sh[t] = v;
    __syncthreads();
    for (int off = 1; off < SCAN_BLK; off <<= 1) {
        int u = (t >= off) ? sh[t - off] : 0;
        __syncthreads();
        sh[t] += u;
        __syncthreads();
    }
    if (t < nb) g_bsum[t] = sh[t] - v;   // exclusive
}

// reads g_cnt, writes g_off/g_cur, re-zeroes g_cnt (deterministic replay).
__global__ __launch_bounds__(SCAN_BLK) void scan_final(int n)
{
    __shared__ int sh[SCAN_BLK];
    int i = blockIdx.x * SCAN_BLK + threadIdx.x;
    int t = threadIdx.x;
    int v = (i < n) ? g_cnt[i] : 0;
    sh[t] = v;
    __syncthreads();
    for (int off = 1; off < SCAN_BLK; off <<= 1) {
        int u = (t >= off) ? sh[t - off] : 0;
        __syncthreads();
        sh[t] += u;
        __syncthreads();
    }
    if (i < n) {
        int excl = sh[t] - v + g_bsum[blockIdx.x];
        g_off[i] = excl;
        g_cur[i] = excl;
        g_cnt[i] = 0;
    }
}

__global__ void scatter_kernel(const int* __restrict__ src,
                               const int* __restrict__ dst, int E)
{
    int i = blockIdx.x * blockDim.x + threadIdx.x;
    if (i < E) {
        int p = atomicAdd(&g_cur[dst[i]], 1);
        g_esrc[p] = src[i];
    }
}

// ---------------- gather: one warp per destination node ------------------
// lane l owns dims [l*4, l*4+4). Interleaved KV: ONE uint4 (16B) per edge
// per lane. 4-way unrolled for MLP (cover L2 hit latency).
__global__ __launch_bounds__(256) void gat_gather(float* __restrict__ out, int n)
{
    int warp = (blockIdx.x * blockDim.x + threadIdx.x) >> 5;
    int lane = threadIdx.x & 31;
    if (warp >= n) return;

    const int t = lane * 4;
    const int start = g_off[warp];
    const int end   = g_cur[warp];

    const float4 q = *(const float4*)(g_Q + (size_t)warp * 128 + t);

    float ax = 0.f, ay = 0.f, az = 0.f, aw = 0.f;
    float den = 0.f;

    int i = start;
    for (; i + 3 < end; i += 4) {
        int s0 = g_esrc[i];
        int s1 = g_esrc[i + 1];
        int s2 = g_esrc[i + 2];
        int s3 = g_esrc[i + 3];
        uint4 kv0 = *(const uint4*)(g_KV + (size_t)s0 * 256 + lane * 8);
        uint4 kv1 = *(const uint4*)(g_KV + (size_t)s1 * 256 + lane * 8);
        uint4 kv2 = *(const uint4*)(g_KV + (size_t)s2 * 256 + lane * 8);
        uint4 kv3 = *(const uint4*)(g_KV + (size_t)s3 * 256 + lane * 8);

        float2 a01, a23;
        a01 = __half22float2(*(__half2*)&kv0.x);
        a23 = __half22float2(*(__half2*)&kv0.y);
        float p0 = q.x * a01.x + q.y * a01.y + q.z * a23.x + q.w * a23.y;
        a01 = __half22float2(*(__half2*)&kv1.x);
        a23 = __half22float2(*(__half2*)&kv1.y);
        float p1 = q.x * a01.x + q.y * a01.y + q.z * a23.x + q.w * a23.y;
        a01 = __half22float2(*(__half2*)&kv2.x);
        a23 = __half22float2(*(__half2*)&kv2.y);
        float p2 = q.x * a01.x + q.y * a01.y + q.z * a23.x + q.w * a23.y;
        a01 = __half22float2(*(__half2*)&kv3.x);
        a23 = __half22float2(*(__half2*)&kv3.y);
        float p3 = q.x * a01.x + q.y * a01.y + q.z * a23.x + q.w * a23.y;

        p0 += __shfl_xor_sync(0xFFFFFFFFu, p0, 1);
        p1 += __shfl_xor_sync(0xFFFFFFFFu, p1, 1);
        p2 += __shfl_xor_sync(0xFFFFFFFFu, p2, 1);
        p3 += __shfl_xor_sync(0xFFFFFFFFu, p3, 1);
        p0 += __shfl_xor_sync(0xFFFFFFFFu, p0, 2);
        p1 += __shfl_xor_sync(0xFFFFFFFFu, p1, 2);
        p2 += __shfl_xor_sync(0xFFFFFFFFu, p2, 2);
        p3 += __shfl_xor_sync(0xFFFFFFFFu, p3, 2);
        float e0 = __expf(p0 * 0.25f);
        float e1 = __expf(p1 * 0.25f);
        float e2 = __expf(p2 * 0.25f);
        float e3 = __expf(p3 * 0.25f);

        float2 v01, v23;
        v01 = __half22float2(*(__half2*)&kv0.z);
        v23 = __half22float2(*(__half2*)&kv0.w);
        ax = fmaf(e0, v01.x, ax); ay = fmaf(e0, v01.y, ay);
        az = fmaf(e0, v23.x, az); aw = fmaf(e0, v23.y, aw);
        v01 = __half22float2(*(__half2*)&kv1.z);
        v23 = __half22float2(*(__half2*)&kv1.w);
        ax = fmaf(e1, v01.x, ax); ay = fmaf(e1, v01.y, ay);
        az = fmaf(e1, v23.x, az); aw = fmaf(e1, v23.y, aw);
        v01 = __half22float2(*(__half2*)&kv2.z);
        v23 = __half22float2(*(__half2*)&kv2.w);
        ax = fmaf(e2, v01.x, ax); ay = fmaf(e2, v01.y, ay);
        az = fmaf(e2, v23.x, az); aw = fmaf(e2, v23.y, aw);
        v01 = __half22float2(*(__half2*)&kv3.z);
        v23 = __half22float2(*(__half2*)&kv3.w);
        ax = fmaf(e3, v01.x, ax); ay = fmaf(e3, v01.y, ay);
        az = fmaf(e3, v23.x, az); aw = fmaf(e3, v23.y, aw);
        den += (e0 + e1) + (e2 + e3);
    }
    for (; i < end; i++) {
        int s = g_esrc[i];
        uint4 kv = *(const uint4*)(g_KV + (size_t)s * 256 + lane * 8);
        float2 k01 = __half22float2(*(__half2*)&kv.x);
        float2 k23 = __half22float2(*(__half2*)&kv.y);
        float p = q.x * k01.x + q.y * k01.y + q.z * k23.x + q.w * k23.y;
        p += __shfl_xor_sync(0xFFFFFFFFu, p, 1);
        p += __shfl_xor_sync(0xFFFFFFFFu, p, 2);
        float e = __expf(p * 0.25f);
        float2 v01 = __half22float2(*(__half2*)&kv.z);
        float2 v23 = __half22float2(*(__half2*)&kv.w);
        ax = fmaf(e, v01.x, ax);
        ay = fmaf(e, v01.y, ay);
        az = fmaf(e, v23.x, az);
        aw = fmaf(e, v23.y, aw);
        den += e;
    }

    float inv = 1.f / den;
    float4 o;
    o.x = ax * inv; o.y = ay * inv; o.z = az * inv; o.w = aw * inv;
    *(float4*)(out + (size_t)warp * 128 + t) = o;
}

// ---------------- launch ------------------------------------------------
// Side stream + events: created lazily on FIRST call (uncaptured correctness
// run), not at static-init. Same work submitted every call -> deterministic.
struct ForkResources {
    cudaStream_t s1;
    cudaEvent_t evFork, evJoin;
    ForkResources() {
        cudaStreamCreateWithFlags(&s1, cudaStreamNonBlocking);
        cudaEventCreateWithFlags(&evFork, cudaEventDisableTiming);
        cudaEventCreateWithFlags(&evJoin, cudaEventDisableTiming);
    }
};

extern "C" void kernel_launch(void* const* d_in, const int* in_sizes, int n_in,
                              void* d_out, int out_size)
{
    static ForkResources fork;   // first call, after harness init

    const float* h  = (const float*)d_in[0];
    const float* wq = (const float*)d_in[1];
    const float* bq = (const float*)d_in[2];
    const float* wk = (const float*)d_in[3];
    const float* bk = (const float*)d_in[4];
    const float* wv = (const float*)d_in[5];
    const float* bv = (const float*)d_in[6];
    const int*  src = (const int*)d_in[7];
    const int*  dst = (const int*)d_in[8];

    const int n = in_sizes[0] / HID;
    const int E = in_sizes[7];
    const int nb = (n + SCAN_BLK - 1) / SCAN_BLK;

    float* out = (float*)d_out;

    // Fork: CSR build on side stream, GEMM on main stream. Join before gather.
    cudaEventRecord(fork.evFork, 0);
    cudaStreamWaitEvent(fork.s1, fork.evFork, 0);

    hist_kernel<<<(E + 255) / 256, 256, 0, fork.s1>>>(dst, E);
    scan_partial<<<nb, SCAN_BLK, 0, fork.s1>>>(n);
    scan_bsums<<<1, SCAN_BLK, 0, fork.s1>>>(nb);
    scan_final<<<nb, SCAN_BLK, 0, fork.s1>>>(n);
    scatter_kernel<<<(E + 255) / 256, 256, 0, fork.s1>>>(src, dst, E);
    cudaEventRecord(fork.evJoin, fork.s1);

    {
        dim3 grid((n + 127) / 128, 3);
        qkv_gemm<<<grid, 256>>>(h, wq, bq, wk, bk, wv, bv, n);
    }

    cudaStreamWaitEvent(0, fork.evJoin, 0);
    gat_gather<<<(n + 7) / 8, 256>>>(out, n);
}

// round 14
// speedup vs baseline: 1.3671x; 1.0336x over previous
#include <cuda_runtime.h>
#include <cuda_fp16.h>
#include <math.h>

// Problem constants (fixed-shape problem)
#define MAXN 50048
#define MAXE 1600000
#define HID 128
#define NH 8
#define HD 16
#define SCAN_BLK 256

// ---------------- device scratch (no allocation allowed) ----------------
__device__ float  g_Q[MAXN * HID];        // fp32 (read once per node)
// Interleaved K/V fp16: per node 256 halves; group g (=dim/4) at offset
// g*8: [K0 K1 K2 K3 V0 V1 V2 V3]. One uint4 per lane per edge.
__device__ __half g_KV[MAXN * 2 * HID];
__device__ int g_cnt[MAXN];               // zero-init; re-zeroed in scan_final
__device__ int g_off[MAXN];
__device__ int g_cur[MAXN];
__device__ int g_esrc[MAXE];
__device__ int g_bsum[512];

// ---------------- QKV GEMM (tf32 tensor cores) ---------------------------
__device__ __forceinline__ float cvt_tf32f(float v)
{
    unsigned r;
    asm("cvt.rna.tf32.f32 %0, %1;" : "=r"(r) : "f"(v));
    return __uint_as_float(r);
}

__global__ __launch_bounds__(256) void qkv_gemm(
    const float* __restrict__ h,
    const float* __restrict__ wq, const float* __restrict__ bq,
    const float* __restrict__ wk, const float* __restrict__ bk,
    const float* __restrict__ wv, const float* __restrict__ bv,
    int n)
{
    const float* W; const float* bias;
    float* outf = 0;
    int kvOff = 0;            // 0 for K, 4 for V (within 8-half group)
    if (blockIdx.y == 0)      { W = wq; bias = bq; outf = g_Q; }
    else if (blockIdx.y == 1) { W = wk; bias = bk; kvOff = 0; }
    else                      { W = wv; bias = bv; kvOff = 4; }

    __shared__ float As[32][132];   // [k][m], tf32-rounded
    __shared__ float Bs[32][132];   // [k][n], tf32-rounded

    const int tid  = threadIdx.x;
    const int lane = tid & 31;
    const int wid  = tid >> 5;          // 0..7
    const int wm   = wid >> 2;          // 0..1 -> M offset wm*64
    const int wn   = wid & 3;           // 0..3 -> N offset wn*32
    const int g    = lane >> 2;         // groupID 0..7
    const int tg   = lane & 3;          // thread-in-group 0..3
    const int row0 = blockIdx.x * 128;

    float c[4][4][4];
#pragma unroll
    for (int mi = 0; mi < 4; mi++)
#pragma unroll
        for (int ni = 0; ni < 4; ni++)
#pragma unroll
            for (int r = 0; r < 4; r++) c[mi][ni][r] = 0.f;

    for (int kk = 0; kk < HID; kk += 32) {
        {
            int m    = tid >> 1;
            int base = (tid & 1) * 16;
            int row  = row0 + m;
#pragma unroll
            for (int i = 0; i < 4; i++) {
                float4 v = make_float4(0.f, 0.f, 0.f, 0.f);
                if (row < n)
                    v = *(const float4*)(h + (size_t)row * HID + kk + base + i * 4);
                As[base + i * 4 + 0][m] = cvt_tf32f(v.x);
                As[base + i * 4 + 1][m] = cvt_tf32f(v.y);
                As[base + i * 4 + 2][m] = cvt_tf32f(v.z);
                As[base + i * 4 + 3][m] = cvt_tf32f(v.w);
            }
        }
        {
            int k    = tid >> 3;
            int base = (tid & 7) * 16;
#pragma unroll
            for (int i = 0; i < 4; i++) {
                float4 v = *(const float4*)(W + (size_t)(kk + k) * 128 + base + i * 4);
                Bs[k][base + i * 4 + 0] = cvt_tf32f(v.x);
                Bs[k][base + i * 4 + 1] = cvt_tf32f(v.y);
                Bs[k][base + i * 4 + 2] = cvt_tf32f(v.z);
                Bs[k][base + i * 4 + 3] = cvt_tf32f(v.w);
            }
        }
        __syncthreads();

#pragma unroll
        for (int ks = 0; ks < 4; ks++) {
            const int k0 = ks * 8;
            unsigned a[4][4];
#pragma unroll
            for (int mi = 0; mi < 4; mi++) {
                int m0 = wm * 64 + mi * 16;
                a[mi][0] = __float_as_uint(As[k0 + tg    ][m0 + g    ]);
                a[mi][1] = __float_as_uint(As[k0 + tg    ][m0 + g + 8]);
                a[mi][2] = __float_as_uint(As[k0 + tg + 4][m0 + g    ]);
                a[mi][3] = __float_as_uint(As[k0 + tg + 4][m0 + g + 8]);
            }
            unsigned b[4][2];
#pragma unroll
            for (int ni = 0; ni < 4; ni++) {
                int n0 = wn * 32 + ni * 8;
                b[ni][0] = __float_as_uint(Bs[k0 + tg    ][n0 + g]);
                b[ni][1] = __float_as_uint(Bs[k0 + tg + 4][n0 + g]);
            }
#pragma unroll
            for (int mi = 0; mi < 4; mi++)
#pragma unroll
                for (int ni = 0; ni < 4; ni++) {
                    asm volatile(
                        "mma.sync.aligned.m16n8k8.row.col.f32.tf32.tf32.f32 "
                        "{%0,%1,%2,%3}, {%4,%5,%6,%7}, {%8,%9}, {%0,%1,%2,%3};"
                        : "+f"(c[mi][ni][0]), "+f"(c[mi][ni][1]),
                          "+f"(c[mi][ni][2]), "+f"(c[mi][ni][3])
                        : "r"(a[mi][0]), "r"(a[mi][1]), "r"(a[mi][2]), "r"(a[mi][3]),
                          "r"(b[ni][0]), "r"(b[ni][1]));
                }
        }
        __syncthreads();
    }

    // epilogue: add bias, store (c0,c1 -> row g; c2,c3 -> row g+8)
#pragma unroll
    for (int ni = 0; ni < 4; ni++) {
        int col = wn * 32 + ni * 8 + tg * 2;
        float bx = bias[col], by = bias[col + 1];
        int kvIdx = ((col >> 2) << 3) + (col & 3) + kvOff;
#pragma unroll
        for (int mi = 0; mi < 4; mi++) {
            int rowA = row0 + wm * 64 + mi * 16 + g;
            int rowB = rowA + 8;
            if (outf) {
                if (rowA < n) {
                    float2 o = make_float2(c[mi][ni][0] + bx, c[mi][ni][1] + by);
                    *(float2*)(outf + (size_t)rowA * 128 + col) = o;
                }
                if (rowB < n) {
                    float2 o = make_float2(c[mi][ni][2] + bx, c[mi][ni][3] + by);
                    *(float2*)(outf + (size_t)rowB * 128 + col) = o;
                }
            } else {
                if (rowA < n) {
                    __half2 o = __floats2half2_rn(c[mi][ni][0] + bx, c[mi][ni][1] + by);
                    *(__half2*)(g_KV + (size_t)rowA * 256 + kvIdx) = o;
                }
                if (rowB < n) {
                    __half2 o = __floats2half2_rn(c[mi][ni][2] + bx, c[mi][ni][3] + by);
                    *(__half2*)(g_KV + (size_t)rowB * 256 + kvIdx) = o;
                }
            }
        }
    }
}

// ---------------- CSR construction (4 edges per thread) -------------------
__global__ void hist_kernel(const int* __restrict__ dst, int E)
{
    int i4 = (blockIdx.x * blockDim.x + threadIdx.x) * 4;
    if (i4 + 3 < E) {
        int4 d = *(const int4*)(dst + i4);
        atomicAdd(&g_cnt[d.x], 1);
        atomicAdd(&g_cnt[d.y], 1);
        atomicAdd(&g_cnt[d.z], 1);
        atomicAdd(&g_cnt[d.w], 1);
    } else {
        for (int i = i4; i < E; i++) atomicAdd(&g_cnt[dst[i]], 1);
    }
}

__global__ __launch_bounds__(SCAN_BLK) void scan_partial(int n)
{
    __shared__ int sh[SCAN_BLK];
    int i = blockIdx.x * SCAN_BLK + threadIdx.x;
    int v = (i < n) ? g_cnt[i] : 0;
    sh[threadIdx.x] = v;
    __syncthreads();
    for (int off = SCAN_BLK / 2; off > 0; off >>= 1) {
        if (threadIdx.x < off) sh[threadIdx.x] += sh[threadIdx.x + off];
        __syncthreads();
    }
    if (threadIdx.x == 0) g_bsum[blockIdx.x] = sh[0];
}

__global__ __launch_bounds__(SCAN_BLK) void scan_bsums(int nb)
{
    __shared__ int sh[SCAN_BLK];
    int t = threadIdx.x;
    int v = (t < nb) ? g_bsum[t] : 0;
    sh[t] = v;
    __syncthreads();
    for (int off = 1; off < SCAN_BLK; off <<= 1) {
        int u = (t >= off) ? sh[t - off] : 0;
        __syncthreads();
        sh[t] += u;
        __syncthreads();
    }
    if (t < nb) g_bsum[t] = sh[t] - v;   // exclusive
}

// reads g_cnt, writes g_off/g_cur, re-zeroes g_cnt (deterministic replay).
__global__ __launch_bounds__(SCAN_BLK) void scan_final(int n)
{
    __shared__ int sh[SCAN_BLK];
    int i = blockIdx.x * SCAN_BLK + threadIdx.x;
    int t = threadIdx.x;
    int v = (i < n) ? g_cnt[i] : 0;
    sh[t] = v;
    __syncthreads();
    for (int off = 1; off < SCAN_BLK; off <<= 1) {
        int u = (t >= off) ? sh[t - off] : 0;
        __syncthreads();
        sh[t] += u;
        __syncthreads();
    }
    if (i < n) {
        int excl = sh[t] - v + g_bsum[blockIdx.x];
        g_off[i] = excl;
        g_cur[i] = excl;
        g_cnt[i] = 0;
    }
}

__global__ void scatter_kernel(const int* __restrict__ src,
                               const int* __restrict__ dst, int E)
{
    int i4 = (blockIdx.x * blockDim.x + threadIdx.x) * 4;
    if (i4 + 3 < E) {
        int4 d = *(const int4*)(dst + i4);
        int4 s = *(const int4*)(src + i4);
        g_esrc[atomicAdd(&g_cur[d.x], 1)] = s.x;
        g_esrc[atomicAdd(&g_cur[d.y], 1)] = s.y;
        g_esrc[atomicAdd(&g_cur[d.z], 1)] = s.z;
        g_esrc[atomicAdd(&g_cur[d.w], 1)] = s.w;
    } else {
        for (int i = i4; i < E; i++)
            g_esrc[atomicAdd(&g_cur[dst[i]], 1)] = src[i];
    }
}

// ---------------- gather: one warp per destination node ------------------
// lane l owns dims [l*4, l*4+4). Interleaved KV: ONE uint4 (16B) per edge
// per lane. 2-way unrolled (proven best: R10).
__global__ __launch_bounds__(256) void gat_gather(float* __restrict__ out, int n)
{
    int warp = (blockIdx.x * blockDim.x + threadIdx.x) >> 5;
    int lane = threadIdx.x & 31;
    if (warp >= n) return;

    const int t = lane * 4;
    const int start = g_off[warp];
    const int end   = g_cur[warp];

    const float4 q = *(const float4*)(g_Q + (size_t)warp * 128 + t);

    float ax = 0.f, ay = 0.f, az = 0.f, aw = 0.f;
    float den = 0.f;

    int i = start;
    for (; i + 1 < end; i += 2) {
        int s0 = g_esrc[i];
        int s1 = g_esrc[i + 1];
        uint4 kv0 = *(const uint4*)(g_KV + (size_t)s0 * 256 + lane * 8);
        uint4 kv1 = *(const uint4*)(g_KV + (size_t)s1 * 256 + lane * 8);

        float2 k01 = __half22float2(*(__half2*)&kv0.x);
        float2 k23 = __half22float2(*(__half2*)&kv0.y);
        float p0 = q.x * k01.x + q.y * k01.y + q.z * k23.x + q.w * k23.y;
        float2 l01 = __half22float2(*(__half2*)&kv1.x);
        float2 l23 = __half22float2(*(__half2*)&kv1.y);
        float p1 = q.x * l01.x + q.y * l01.y + q.z * l23.x + q.w * l23.y;

        p0 += __shfl_xor_sync(0xFFFFFFFFu, p0, 1);
        p1 += __shfl_xor_sync(0xFFFFFFFFu, p1, 1);
        p0 += __shfl_xor_sync(0xFFFFFFFFu, p0, 2);
        p1 += __shfl_xor_sync(0xFFFFFFFFu, p1, 2);
        float e0 = __expf(p0 * 0.25f);
        float e1 = __expf(p1 * 0.25f);

        float2 v01 = __half22float2(*(__half2*)&kv0.z);
        float2 v23 = __half22float2(*(__half2*)&kv0.w);
        float2 w01 = __half22float2(*(__half2*)&kv1.z);
        float2 w23 = __half22float2(*(__half2*)&kv1.w);
        ax = fmaf(e0, v01.x, fmaf(e1, w01.x, ax));
        ay = fmaf(e0, v01.y, fmaf(e1, w01.y, ay));
        az = fmaf(e0, v23.x, fmaf(e1, w23.x, az));
        aw = fmaf(e0, v23.y, fmaf(e1, w23.y, aw));
        den += e0 + e1;
    }
    if (i < end) {
        int s = g_esrc[i];
        uint4 kv = *(const uint4*)(g_KV + (size_t)s * 256 + lane * 8);
        float2 k01 = __half22float2(*(__half2*)&kv.x);
        float2 k23 = __half22float2(*(__half2*)&kv.y);
        float p = q.x * k01.x + q.y * k01.y + q.z * k23.x + q.w * k23.y;
        p += __shfl_xor_sync(0xFFFFFFFFu, p, 1);
        p += __shfl_xor_sync(0xFFFFFFFFu, p, 2);
        float e = __expf(p * 0.25f);
        float2 v01 = __half22float2(*(__half2*)&kv.z);
        float2 v23 = __half22float2(*(__half2*)&kv.w);
        ax = fmaf(e, v01.x, ax);
        ay = fmaf(e, v01.y, ay);
        az = fmaf(e, v23.x, az);
        aw = fmaf(e, v23.y, aw);
        den += e;
    }

    float inv = 1.f / den;
    float4 o;
    o.x = ax * inv; o.y = ay * inv; o.z = az * inv; o.w = aw * inv;
    *(float4*)(out + (size_t)warp * 128 + t) = o;
}

// ---------------- launch ------------------------------------------------
// Side stream + events: created lazily on FIRST call (uncaptured correctness
// run), not at static-init. Same work submitted every call -> deterministic.
struct ForkResources {
    cudaStream_t s1;
    cudaEvent_t evFork, evJoin;
    ForkResources() {
        cudaStreamCreateWithFlags(&s1, cudaStreamNonBlocking);
        cudaEventCreateWithFlags(&evFork, cudaEventDisableTiming);
        cudaEventCreateWithFlags(&evJoin, cudaEventDisableTiming);
    }
};

extern "C" void kernel_launch(void* const* d_in, const int* in_sizes, int n_in,
                              void* d_out, int out_size)
{
    static ForkResources fork;   // first call, after harness init

    const float* h  = (const float*)d_in[0];
    const float* wq = (const float*)d_in[1];
    const float* bq = (const float*)d_in[2];
    const float* wk = (const float*)d_in[3];
    const float* bk = (const float*)d_in[4];
    const float* wv = (const float*)d_in[5];
    const float* bv = (const float*)d_in[6];
    const int*  src = (const int*)d_in[7];
    const int*  dst = (const int*)d_in[8];

    const int n = in_sizes[0] / HID;
    const int E = in_sizes[7];
    const int nb = (n + SCAN_BLK - 1) / SCAN_BLK;
    const int e4blocks = ((E + 3) / 4 + 255) / 256;

    float* out = (float*)d_out;

    // Fork: CSR build on side stream, GEMM on main stream. Join before gather.
    cudaEventRecord(fork.evFork, 0);
    cudaStreamWaitEvent(fork.s1, fork.evFork, 0);

    hist_kernel<<<e4blocks, 256, 0, fork.s1>>>(dst, E);
    scan_partial<<<nb, SCAN_BLK, 0, fork.s1>>>(n);
    scan_bsums<<<1, SCAN_BLK, 0, fork.s1>>>(nb);
    scan_final<<<nb, SCAN_BLK, 0, fork.s1>>>(n);
    scatter_kernel<<<e4blocks, 256, 0, fork.s1>>>(src, dst, E);
    cudaEventRecord(fork.evJoin, fork.s1);

    {
        dim3 grid((n + 127) / 128, 3);
        qkv_gemm<<<grid, 256>>>(h, wq, bq, wk, bk, wv, bv, n);
    }

    cudaStreamWaitEvent(0, fork.evJoin, 0);
    gat_gather<<<(n + 7) / 8, 256>>>(out, n);
}

// round 15
// speedup vs baseline: 1.3800x; 1.0094x over previous
#include <cuda_runtime.h>
#include <cuda_fp16.h>
#include <math.h>

// Problem constants (fixed-shape problem)
#define MAXN 50048
#define MAXE 1600000
#define HID 128
#define NH 8
#define HD 16
#define SCAN_BLK 256

// ---------------- device scratch (no allocation allowed) ----------------
__device__ float  g_Q[MAXN * HID];        // fp32 (read once per node)
// Interleaved K/V fp16: per node 256 halves; group g (=dim/4) at offset
// g*8: [K0 K1 K2 K3 V0 V1 V2 V3]. One uint4 per lane per edge.
__device__ __half g_KV[MAXN * 2 * HID];
__device__ int g_cnt[MAXN];               // zero-init; re-zeroed in scan_final
__device__ int g_off[MAXN];
__device__ int g_cur[MAXN];
__device__ int g_esrc[MAXE];
__device__ int g_bsum[512];

// ---------------- QKV GEMM (tf32 tensor cores) ---------------------------
// C[n,128] = h[n,128] @ W[128,128] + b.  Block tile 128x128, BK=32.
// 256 threads = 8 warps 2(M) x 4(N); warp tile 64x32; mma.m16n8k8.tf32.
// Epilogue stages the output tile in smem (aliasing As/Bs) for coalesced
// global stores (fixes 8x sector amplification of the fragment stores).
__device__ __forceinline__ float cvt_tf32f(float v)
{
    unsigned r;
    asm("cvt.rna.tf32.f32 %0, %1;" : "=r"(r) : "f"(v));
    return __uint_as_float(r);
}

__global__ __launch_bounds__(256) void qkv_gemm(
    const float* __restrict__ h,
    const float* __restrict__ wq, const float* __restrict__ bq,
    const float* __restrict__ wk, const float* __restrict__ bk,
    const float* __restrict__ wv, const float* __restrict__ bv,
    int n)
{
    const float* W; const float* bias;
    float* outf = 0;
    int kvOff = 0;            // 0 for K, 4 for V (within 8-half group)
    if (blockIdx.y == 0)      { W = wq; bias = bq; outf = g_Q; }
    else if (blockIdx.y == 1) { W = wk; bias = bk; kvOff = 0; }
    else                      { W = wv; bias = bv; kvOff = 4; }

    // 33792 bytes shared, aliased three ways:
    //   mainloop: As[32][132] f32 (16896B) + Bs[32][132] f32 (16896B)
    //   KV epilogue: St[128][132] half (33792B)
    //   Q epilogue:  Sf[64][132] f32 (33792B)
    __shared__ __align__(16) char smemRaw[33792];
    float  (*As)[132] = reinterpret_cast<float(*)[132]>(smemRaw);
    float  (*Bs)[132] = reinterpret_cast<float(*)[132]>(smemRaw + 16896);
    __half (*St)[132] = reinterpret_cast<__half(*)[132]>(smemRaw);
    float  (*Sf)[132] = reinterpret_cast<float(*)[132]>(smemRaw);

    const int tid  = threadIdx.x;
    const int lane = tid & 31;
    const int wid  = tid >> 5;          // 0..7
    const int wm   = wid >> 2;          // 0..1 -> M offset wm*64
    const int wn   = wid & 3;           // 0..3 -> N offset wn*32
    const int g    = lane >> 2;         // groupID 0..7
    const int tg   = lane & 3;          // thread-in-group 0..3
    const int row0 = blockIdx.x * 128;

    float c[4][4][4];
#pragma unroll
    for (int mi = 0; mi < 4; mi++)
#pragma unroll
        for (int ni = 0; ni < 4; ni++)
#pragma unroll
            for (int r = 0; r < 4; r++) c[mi][ni][r] = 0.f;

    for (int kk = 0; kk < HID; kk += 32) {
        {
            int m    = tid >> 1;
            int base = (tid & 1) * 16;
            int row  = row0 + m;
#pragma unroll
            for (int i = 0; i < 4; i++) {
                float4 v = make_float4(0.f, 0.f, 0.f, 0.f);
                if (row < n)
                    v = *(const float4*)(h + (size_t)row * HID + kk + base + i * 4);
                As[base + i * 4 + 0][m] = cvt_tf32f(v.x);
                As[base + i * 4 + 1][m] = cvt_tf32f(v.y);
                As[base + i * 4 + 2][m] = cvt_tf32f(v.z);
                As[base + i * 4 + 3][m] = cvt_tf32f(v.w);
            }
        }
        {
            int k    = tid >> 3;
            int base = (tid & 7) * 16;
#pragma unroll
            for (int i = 0; i < 4; i++) {
                float4 v = *(const float4*)(W + (size_t)(kk + k) * 128 + base + i * 4);
                Bs[k][base + i * 4 + 0] = cvt_tf32f(v.x);
                Bs[k][base + i * 4 + 1] = cvt_tf32f(v.y);
                Bs[k][base + i * 4 + 2] = cvt_tf32f(v.z);
                Bs[k][base + i * 4 + 3] = cvt_tf32f(v.w);
            }
        }
        __syncthreads();

#pragma unroll
        for (int ks = 0; ks < 4; ks++) {
            const int k0 = ks * 8;
            unsigned a[4][4];
#pragma unroll
            for (int mi = 0; mi < 4; mi++) {
                int m0 = wm * 64 + mi * 16;
                a[mi][0] = __float_as_uint(As[k0 + tg    ][m0 + g    ]);
                a[mi][1] = __float_as_uint(As[k0 + tg    ][m0 + g + 8]);
                a[mi][2] = __float_as_uint(As[k0 + tg + 4][m0 + g    ]);
                a[mi][3] = __float_as_uint(As[k0 + tg + 4][m0 + g + 8]);
            }
            unsigned b[4][2];
#pragma unroll
            for (int ni = 0; ni < 4; ni++) {
                int n0 = wn * 32 + ni * 8;
                b[ni][0] = __float_as_uint(Bs[k0 + tg    ][n0 + g]);
                b[ni][1] = __float_as_uint(Bs[k0 + tg + 4][n0 + g]);
            }
#pragma unroll
            for (int mi = 0; mi < 4; mi++)
#pragma unroll
                for (int ni = 0; ni < 4; ni++) {
                    asm volatile(
                        "mma.sync.aligned.m16n8k8.row.col.f32.tf32.tf32.f32 "
                        "{%0,%1,%2,%3}, {%4,%5,%6,%7}, {%8,%9}, {%0,%1,%2,%3};"
                        : "+f"(c[mi][ni][0]), "+f"(c[mi][ni][1]),
                          "+f"(c[mi][ni][2]), "+f"(c[mi][ni][3])
                        : "r"(a[mi][0]), "r"(a[mi][1]), "r"(a[mi][2]), "r"(a[mi][3]),
                          "r"(b[ni][0]), "r"(b[ni][1]));
                }
        }
        __syncthreads();
    }

    // ---------------- staged, coalesced epilogue ----------------
    if (outf) {
        // Q (fp32): two passes of 64 rows through Sf
#pragma unroll
        for (int p = 0; p < 2; p++) {
            __syncthreads();
            if (wm == p) {
#pragma unroll
                for (int ni = 0; ni < 4; ni++) {
                    int col = wn * 32 + ni * 8 + tg * 2;
                    float bx = bias[col], by = bias[col + 1];
#pragma unroll
                    for (int mi = 0; mi < 4; mi++) {
                        int r = mi * 16 + g;         // 0..63 local
                        Sf[r][col]     = c[mi][ni][0] + bx;
                        Sf[r][col + 1] = c[mi][ni][1] + by;
                        Sf[r + 8][col]     = c[mi][ni][2] + bx;
                        Sf[r + 8][col + 1] = c[mi][ni][3] + by;
                    }
                }
            }
            __syncthreads();
            for (int idx = tid; idx < 64 * 32; idx += 256) {
                int r  = idx >> 5;
                int c4 = (idx & 31) * 4;
                int row = row0 + p * 64 + r;
                if (row < n) {
                    float4 v = *(float4*)&Sf[r][c4];
                    *(float4*)(outf + (size_t)row * 128 + c4) = v;
                }
            }
        }
    } else {
        // K or V (fp16): stage full 128x128 half tile, write 8B groups
#pragma unroll
        for (int ni = 0; ni < 4; ni++) {
            int col = wn * 32 + ni * 8 + tg * 2;
            float bx = bias[col], by = bias[col + 1];
#pragma unroll
            for (int mi = 0; mi < 4; mi++) {
                int rA = wm * 64 + mi * 16 + g;
                *(__half2*)&St[rA][col] =
                    __floats2half2_rn(c[mi][ni][0] + bx, c[mi][ni][1] + by);
                *(__half2*)&St[rA + 8][col] =
                    __floats2half2_rn(c[mi][ni][2] + bx, c[mi][ni][3] + by);
            }
        }
        __syncthreads();
        for (int idx = tid; idx < 128 * 32; idx += 256) {
            int r   = idx >> 5;
            int grp = idx & 31;
            int row = row0 + r;
            if (row < n) {
                uint2 v = *(uint2*)&St[r][grp * 4];
                *(uint2*)(g_KV + (size_t)row * 256 + grp * 8 + kvOff) = v;
            }
        }
    }
}

// ---------------- CSR construction (4 edges per thread) -------------------
__global__ void hist_kernel(const int* __restrict__ dst, int E)
{
    int i4 = (blockIdx.x * blockDim.x + threadIdx.x) * 4;
    if (i4 + 3 < E) {
        int4 d = *(const int4*)(dst + i4);
        atomicAdd(&g_cnt[d.x], 1);
        atomicAdd(&g_cnt[d.y], 1);
        atomicAdd(&g_cnt[d.z], 1);
        atomicAdd(&g_cnt[d.w], 1);
    } else {
        for (int i = i4; i < E; i++) atomicAdd(&g_cnt[dst[i]], 1);
    }
}

__global__ __launch_bounds__(SCAN_BLK) void scan_partial(int n)
{
    __shared__ int sh[SCAN_BLK];
    int i = blockIdx.x * SCAN_BLK + threadIdx.x;
    int v = (i < n) ? g_cnt[i] : 0;
    sh[threadIdx.x] = v;
    __syncthreads();
    for (int off = SCAN_BLK / 2; off > 0; off >>= 1) {
        if (threadIdx.x < off) sh[threadIdx.x] += sh[threadIdx.x + off];
        __syncthreads();
    }
    if (threadIdx.x == 0) g_bsum[blockIdx.x] = sh[0];
}

__global__ __launch_bounds__(SCAN_BLK) void scan_bsums(int nb)
{
    __shared__ int sh[SCAN_BLK];
    int t = threadIdx.x;
    int v = (t < nb) ? g_bsum[t] : 0;
    sh[t] = v;
    __syncthreads();
    for (int off = 1; off < SCAN_BLK; off <<= 1) {
        int u = (t >= off) ? sh[t - off] : 0;
        __syncthreads();
        sh[t] += u;
        __syncthreads();
    }
    if (t < nb) g_bsum[t] = sh[t] - v;   // exclusive
}

// reads g_cnt, writes g_off/g_cur, re-zeroes g_cnt (deterministic replay).
__global__ __launch_bounds__(SCAN_BLK) void scan_final(int n)
{
    __shared__ int sh[SCAN_BLK];
    int i = blockIdx.x * SCAN_BLK + threadIdx.x;
    int t = threadIdx.x;
    int v = (i < n) ? g_cnt[i] : 0;
    sh[t] = v;
    __syncthreads();
    for (int off = 1; off < SCAN_BLK; off <<= 1) {
        int u = (t >= off) ? sh[t - off] : 0;
        __syncthreads();
        sh[t] += u;
        __syncthreads();
    }
    if (i < n) {
        int excl = sh[t] - v + g_bsum[blockIdx.x];
        g_off[i] = excl;
        g_cur[i] = excl;
        g_cnt[i] = 0;
    }
}

__global__ void scatter_kernel(const int* __restrict__ src,
                               const int* __restrict__ dst, int E)
{
    int i4 = (blockIdx.x * blockDim.x + threadIdx.x) * 4;
    if (i4 + 3 < E) {
        int4 d = *(const int4*)(dst + i4);
        int4 s = *(const int4*)(src + i4);
        g_esrc[atomicAdd(&g_cur[d.x], 1)] = s.x;
        g_esrc[atomicAdd(&g_cur[d.y], 1)] = s.y;
        g_esrc[atomicAdd(&g_cur[d.z], 1)] = s.z;
        g_esrc[atomicAdd(&g_cur[d.w], 1)] = s.w;
    } else {
        for (int i = i4; i < E; i++)
            g_esrc[atomicAdd(&g_cur[dst[i]], 1)] = src[i];
    }
}

// ---------------- gather: one warp per destination node ------------------
// lane l owns dims [l*4, l*4+4). Interleaved KV: ONE uint4 (16B) per edge
// per lane. 2-way unrolled (proven best: R10).
__global__ __launch_bounds__(256) void gat_gather(float* __restrict__ out, int n)
{
    int warp = (blockIdx.x * blockDim.x + threadIdx.x) >> 5;
    int lane = threadIdx.x & 31;
    if (warp >= n) return;

    const int t = lane * 4;
    const int start = g_off[warp];
    const int end   = g_cur[warp];

    const float4 q = *(const float4*)(g_Q + (size_t)warp * 128 + t);

    float ax = 0.f, ay = 0.f, az = 0.f, aw = 0.f;
    float den = 0.f;

    int i = start;
    for (; i + 1 < end; i += 2) {
        int s0 = g_esrc[i];
        int s1 = g_esrc[i + 1];
        uint4 kv0 = *(const uint4*)(g_KV + (size_t)s0 * 256 + lane * 8);
        uint4 kv1 = *(const uint4*)(g_KV + (size_t)s1 * 256 + lane * 8);

        float2 k01 = __half22float2(*(__half2*)&kv0.x);
        float2 k23 = __half22float2(*(__half2*)&kv0.y);
        float p0 = q.x * k01.x + q.y * k01.y + q.z * k23.x + q.w * k23.y;
        float2 l01 = __half22float2(*(__half2*)&kv1.x);
        float2 l23 = __half22float2(*(__half2*)&kv1.y);
        float p1 = q.x * l01.x + q.y * l01.y + q.z * l23.x + q.w * l23.y;

        p0 += __shfl_xor_sync(0xFFFFFFFFu, p0, 1);
        p1 += __shfl_xor_sync(0xFFFFFFFFu, p1, 1);
        p0 += __shfl_xor_sync(0xFFFFFFFFu, p0, 2);
        p1 += __shfl_xor_sync(0xFFFFFFFFu, p1, 2);
        float e0 = __expf(p0 * 0.25f);
        float e1 = __expf(p1 * 0.25f);

        float2 v01 = __half22float2(*(__half2*)&kv0.z);
        float2 v23 = __half22float2(*(__half2*)&kv0.w);
        float2 w01 = __half22float2(*(__half2*)&kv1.z);
        float2 w23 = __half22float2(*(__half2*)&kv1.w);
        ax = fmaf(e0, v01.x, fmaf(e1, w01.x, ax));
        ay = fmaf(e0, v01.y, fmaf(e1, w01.y, ay));
        az = fmaf(e0, v23.x, fmaf(e1, w23.x, az));
        aw = fmaf(e0, v23.y, fmaf(e1, w23.y, aw));
        den += e0 + e1;
    }
    if (i < end) {
        int s = g_esrc[i];
        uint4 kv = *(const uint4*)(g_KV + (size_t)s * 256 + lane * 8);
        float2 k01 = __half22float2(*(__half2*)&kv.x);
        float2 k23 = __half22float2(*(__half2*)&kv.y);
        float p = q.x * k01.x + q.y * k01.y + q.z * k23.x + q.w * k23.y;
        p += __shfl_xor_sync(0xFFFFFFFFu, p, 1);
        p += __shfl_xor_sync(0xFFFFFFFFu, p, 2);
        float e = __expf(p * 0.25f);
        float2 v01 = __half22float2(*(__half2*)&kv.z);
        float2 v23 = __half22float2(*(__half2*)&kv.w);
        ax = fmaf(e, v01.x, ax);
        ay = fmaf(e, v01.y, ay);
        az = fmaf(e, v23.x, az);
        aw = fmaf(e, v23.y, aw);
        den += e;
    }

    float inv = 1.f / den;
    float4 o;
    o.x = ax * inv; o.y = ay * inv; o.z = az * inv; o.w = aw * inv;
    *(float4*)(out + (size_t)warp * 128 + t) = o;
}

// ---------------- launch ------------------------------------------------
// Side stream + events: created lazily on FIRST call (uncaptured correctness
// run), not at static-init. Same work submitted every call -> deterministic.
struct ForkResources {
    cudaStream_t s1;
    cudaEvent_t evFork, evJoin;
    ForkResources() {
        cudaStreamCreateWithFlags(&s1, cudaStreamNonBlocking);
        cudaEventCreateWithFlags(&evFork, cudaEventDisableTiming);
        cudaEventCreateWithFlags(&evJoin, cudaEventDisableTiming);
    }
};

extern "C" void kernel_launch(void* const* d_in, const int* in_sizes, int n_in,
                              void* d_out, int out_size)
{
    static ForkResources fork;   // first call, after harness init

    const float* h  = (const float*)d_in[0];
    const float* wq = (const float*)d_in[1];
    const float* bq = (const float*)d_in[2];
    const float* wk = (const float*)d_in[3];
    const float* bk = (const float*)d_in[4];
    const float* wv = (const float*)d_in[5];
    const float* bv = (const float*)d_in[6];
    const int*  src = (const int*)d_in[7];
    const int*  dst = (const int*)d_in[8];

    const int n = in_sizes[0] / HID;
    const int E = in_sizes[7];
    const int nb = (n + SCAN_BLK - 1) / SCAN_BLK;
    const int e4blocks = ((E + 3) / 4 + 255) / 256;

    float* out = (float*)d_out;

    // Fork: CSR build on side stream, GEMM on main stream. Join before gather.
    cudaEventRecord(fork.evFork, 0);
    cudaStreamWaitEvent(fork.s1, fork.evFork, 0);

    hist_kernel<<<e4blocks, 256, 0, fork.s1>>>(dst, E);
    scan_partial<<<nb, SCAN_BLK, 0, fork.s1>>>(n);
    scan_bsums<<<1, SCAN_BLK, 0, fork.s1>>>(nb);
    scan_final<<<nb, SCAN_BLK, 0, fork.s1>>>(n);
    scatter_kernel<<<e4blocks, 256, 0, fork.s1>>>(src, dst, E);
    cudaEventRecord(fork.evJoin, fork.s1);

    {
        dim3 grid((n + 127) / 128, 3);
        qkv_gemm<<<grid, 256>>>(h, wq, bq, wk, bk, wv, bv, n);
    }

    cudaStreamWaitEvent(0, fork.evJoin, 0);
    gat_gather<<<(n + 7) / 8, 256>>>(out, n);
}

// round 17
// speedup vs baseline: 1.4016x; 1.0157x over previous
#include <cuda_runtime.h>
#include <cuda_fp16.h>
#include <math.h>

// Problem constants (fixed-shape problem)
#define MAXN 50048
#define MAXE 1600000
#define HID 128
#define NH 8
#define HD 16
#define SCAN_BLK 256

// ---------------- device scratch (no allocation allowed) ----------------
__device__ float  g_Q[MAXN * HID];        // fp32 (read once per node)
// Interleaved K/V fp16: per node 256 halves; group g (=dim/4) at offset
// g*8: [K0 K1 K2 K3 V0 V1 V2 V3]. One uint4 per lane per edge.
__device__ __half g_KV[MAXN * 2 * HID];
__device__ int g_cnt[MAXN];               // zero-init; re-zeroed in scan_final
__device__ int g_off[MAXN];
__device__ int g_cur[MAXN];               // holds END offset after scan_final
__device__ int g_epos[MAXE];              // per-edge rank within its dst bucket
__device__ int g_esrc[MAXE];
__device__ int g_bsum[512];

// ---------------- QKV GEMM (tf32 tensor cores) ---------------------------
// C[n,128] = h[n,128] @ W[128,128] + b.  Block tile 128x128, BK=32.
// Staged smem epilogue for coalesced stores.
__device__ __forceinline__ float cvt_tf32f(float v)
{
    unsigned r;
    asm("cvt.rna.tf32.f32 %0, %1;" : "=r"(r) : "f"(v));
    return __uint_as_float(r);
}

__global__ __launch_bounds__(256) void qkv_gemm(
    const float* __restrict__ h,
    const float* __restrict__ wq, const float* __restrict__ bq,
    const float* __restrict__ wk, const float* __restrict__ bk,
    const float* __restrict__ wv, const float* __restrict__ bv,
    int n)
{
    const float* W; const float* bias;
    float* outf = 0;
    int kvOff = 0;            // 0 for K, 4 for V (within 8-half group)
    if (blockIdx.y == 0)      { W = wq; bias = bq; outf = g_Q; }
    else if (blockIdx.y == 1) { W = wk; bias = bk; kvOff = 0; }
    else                      { W = wv; bias = bv; kvOff = 4; }

    __shared__ __align__(16) char smemRaw[33792];
    float  (*As)[132] = reinterpret_cast<float(*)[132]>(smemRaw);
    float  (*Bs)[132] = reinterpret_cast<float(*)[132]>(smemRaw + 16896);
    __half (*St)[132] = reinterpret_cast<__half(*)[132]>(smemRaw);
    float  (*Sf)[132] = reinterpret_cast<float(*)[132]>(smemRaw);

    const int tid  = threadIdx.x;
    const int lane = tid & 31;
    const int wid  = tid >> 5;
    const int wm   = wid >> 2;
    const int wn   = wid & 3;
    const int g    = lane >> 2;
    const int tg   = lane & 3;
    const int row0 = blockIdx.x * 128;

    float c[4][4][4];
#pragma unroll
    for (int mi = 0; mi < 4; mi++)
#pragma unroll
        for (int ni = 0; ni < 4; ni++)
#pragma unroll
            for (int r = 0; r < 4; r++) c[mi][ni][r] = 0.f;

    for (int kk = 0; kk < HID; kk += 32) {
        {
            int m    = tid >> 1;
            int base = (tid & 1) * 16;
            int row  = row0 + m;
#pragma unroll
            for (int i = 0; i < 4; i++) {
                float4 v = make_float4(0.f, 0.f, 0.f, 0.f);
                if (row < n)
                    v = *(const float4*)(h + (size_t)row * HID + kk + base + i * 4);
                As[base + i * 4 + 0][m] = cvt_tf32f(v.x);
                As[base + i * 4 + 1][m] = cvt_tf32f(v.y);
                As[base + i * 4 + 2][m] = cvt_tf32f(v.z);
                As[base + i * 4 + 3][m] = cvt_tf32f(v.w);
            }
        }
        {
            int k    = tid >> 3;
            int base = (tid & 7) * 16;
#pragma unroll
            for (int i = 0; i < 4; i++) {
                float4 v = *(const float4*)(W + (size_t)(kk + k) * 128 + base + i * 4);
                Bs[k][base + i * 4 + 0] = cvt_tf32f(v.x);
                Bs[k][base + i * 4 + 1] = cvt_tf32f(v.y);
                Bs[k][base + i * 4 + 2] = cvt_tf32f(v.z);
                Bs[k][base + i * 4 + 3] = cvt_tf32f(v.w);
            }
        }
        __syncthreads();

#pragma unroll
        for (int ks = 0; ks < 4; ks++) {
            const int k0 = ks * 8;
            unsigned a[4][4];
#pragma unroll
            for (int mi = 0; mi < 4; mi++) {
                int m0 = wm * 64 + mi * 16;
                a[mi][0] = __float_as_uint(As[k0 + tg    ][m0 + g    ]);
                a[mi][1] = __float_as_uint(As[k0 + tg    ][m0 + g + 8]);
                a[mi][2] = __float_as_uint(As[k0 + tg + 4][m0 + g    ]);
                a[mi][3] = __float_as_uint(As[k0 + tg + 4][m0 + g + 8]);
            }
            unsigned b[4][2];
#pragma unroll
            for (int ni = 0; ni < 4; ni++) {
                int n0 = wn * 32 + ni * 8;
                b[ni][0] = __float_as_uint(Bs[k0 + tg    ][n0 + g]);
                b[ni][1] = __float_as_uint(Bs[k0 + tg + 4][n0 + g]);
            }
#pragma unroll
            for (int mi = 0; mi < 4; mi++)
#pragma unroll
                for (int ni = 0; ni < 4; ni++) {
                    asm volatile(
                        "mma.sync.aligned.m16n8k8.row.col.f32.tf32.tf32.f32 "
                        "{%0,%1,%2,%3}, {%4,%5,%6,%7}, {%8,%9}, {%0,%1,%2,%3};"
                        : "+f"(c[mi][ni][0]), "+f"(c[mi][ni][1]),
                          "+f"(c[mi][ni][2]), "+f"(c[mi][ni][3])
                        : "r"(a[mi][0]), "r"(a[mi][1]), "r"(a[mi][2]), "r"(a[mi][3]),
                          "r"(b[ni][0]), "r"(b[ni][1]));
                }
        }
        __syncthreads();
    }

    // ---------------- staged, coalesced epilogue ----------------
    if (outf) {
#pragma unroll
        for (int p = 0; p < 2; p++) {
            __syncthreads();
            if (wm == p) {
#pragma unroll
                for (int ni = 0; ni < 4; ni++) {
                    int col = wn * 32 + ni * 8 + tg * 2;
                    float bx = bias[col], by = bias[col + 1];
#pragma unroll
                    for (int mi = 0; mi < 4; mi++) {
                        int r = mi * 16 + g;
                        Sf[r][col]     = c[mi][ni][0] + bx;
                        Sf[r][col + 1] = c[mi][ni][1] + by;
                        Sf[r + 8][col]     = c[mi][ni][2] + bx;
                        Sf[r + 8][col + 1] = c[mi][ni][3] + by;
                    }
                }
            }
            __syncthreads();
            for (int idx = tid; idx < 64 * 32; idx += 256) {
                int r  = idx >> 5;
                int c4 = (idx & 31) * 4;
                int row = row0 + p * 64 + r;
                if (row < n) {
                    float4 v = *(float4*)&Sf[r][c4];
                    *(float4*)(outf + (size_t)row * 128 + c4) = v;
                }
            }
        }
    } else {
#pragma unroll
        for (int ni = 0; ni < 4; ni++) {
            int col = wn * 32 + ni * 8 + tg * 2;
            float bx = bias[col], by = bias[col + 1];
#pragma unroll
            for (int mi = 0; mi < 4; mi++) {
                int rA = wm * 64 + mi * 16 + g;
                *(__half2*)&St[rA][col] =
                    __floats2half2_rn(c[mi][ni][0] + bx, c[mi][ni][1] + by);
                *(__half2*)&St[rA + 8][col] =
                    __floats2half2_rn(c[mi][ni][2] + bx, c[mi][ni][3] + by);
            }
        }
        __syncthreads();
        for (int idx = tid; idx < 128 * 32; idx += 256) {
            int r   = idx >> 5;
            int grp = idx & 31;
            int row = row0 + r;
            if (row < n) {
                uint2 v = *(uint2*)&St[r][grp * 4];
                *(uint2*)(g_KV + (size_t)row * 256 + grp * 8 + kvOff) = v;
            }
        }
    }
}

// ---------------- CSR construction --------------------------------------
// hist ALSO records each edge's rank within its dst bucket (atomic return
// value) so scatter needs NO atomics.
__global__ void hist_kernel(const int* __restrict__ dst, int E)
{
    int i4 = (blockIdx.x * blockDim.x + threadIdx.x) * 4;
    if (i4 + 3 < E) {
        int4 d = *(const int4*)(dst + i4);
        int4 p;
        p.x = atomicAdd(&g_cnt[d.x], 1);
        p.y = atomicAdd(&g_cnt[d.y], 1);
        p.z = atomicAdd(&g_cnt[d.z], 1);
        p.w = atomicAdd(&g_cnt[d.w], 1);
        *(int4*)(g_epos + i4) = p;
    } else {
        for (int i = i4; i < E; i++)
            g_epos[i] = atomicAdd(&g_cnt[dst[i]], 1);
    }
}

__global__ __launch_bounds__(SCAN_BLK) void scan_partial(int n)
{
    __shared__ int sh[SCAN_BLK];
    int i = blockIdx.x * SCAN_BLK + threadIdx.x;
    int v = (i < n) ? g_cnt[i] : 0;
    sh[threadIdx.x] = v;
    __syncthreads();
    for (int off = SCAN_BLK / 2; off > 0; off >>= 1) {
        if (threadIdx.x < off) sh[threadIdx.x] += sh[threadIdx.x + off];
        __syncthreads();
    }
    if (threadIdx.x == 0) g_bsum[blockIdx.x] = sh[0];
}

__global__ __launch_bounds__(SCAN_BLK) void scan_bsums(int nb)
{
    __shared__ int sh[SCAN_BLK];
    int t = threadIdx.x;
    int v = (t < nb) ? g_bsum[t] : 0;
    sh[t] = v;
    __syncthreads();
    for (int off = 1; off < SCAN_BLK; off <<= 1) {
        int u = (t >= off) ? sh[t - off] : 0;
        __syncthreads();
        sh[t] += u;
        __syncthreads();
    }
    if (t < nb) g_bsum[t] = sh[t] - v;   // exclusive
}

// writes g_off (start) and g_cur (END = start + count); re-zeroes g_cnt.
__global__ __launch_bounds__(SCAN_BLK) void scan_final(int n)
{
    __shared__ int sh[SCAN_BLK];
    int i = blockIdx.x * SCAN_BLK + threadIdx.x;
    int t = threadIdx.x;
    int v = (i < n) ? g_cnt[i] : 0;
    sh[t] = v;
    __syncthreads();
    for (int off = 1; off < SCAN_BLK; off <<= 1) {
        int u = (t >= off) ? sh[t - off] : 0;
        __syncthreads();
        sh[t] += u;
        __syncthreads();
    }
    if (i < n) {
        int excl = sh[t] - v + g_bsum[blockIdx.x];
        g_off[i] = excl;
        g_cur[i] = excl + v;      // end offset
        g_cnt[i] = 0;
    }
}

// atomic-free scatter: position = off[dst] + per-edge rank from hist.
__global__ void scatter_kernel(const int* __restrict__ src,
                               const int* __restrict__ dst, int E)
{
    int i4 = (blockIdx.x * blockDim.x + threadIdx.x) * 4;
    if (i4 + 3 < E) {
        int4 d = *(const int4*)(dst + i4);
        int4 s = *(const int4*)(src + i4);
        int4 p = *(const int4*)(g_epos + i4);
        g_esrc[g_off[d.x] + p.x] = s.x;
        g_esrc[g_off[d.y] + p.y] = s.y;
        g_esrc[g_off[d.z] + p.z] = s.z;
        g_esrc[g_off[d.w] + p.w] = s.w;
    } else {
        for (int i = i4; i < E; i++)
            g_esrc[g_off[dst[i]] + g_epos[i]] = src[i];
    }
}

// ---------------- gather: one warp per destination node ------------------
// 64-thread blocks (2 warps) for fine-grained HW scheduling of the
// Poisson-degree tail. Interleaved KV: one uint4 per edge per lane.
__global__ __launch_bounds__(64) void gat_gather(float* __restrict__ out, int n)
{
    int warp = (blockIdx.x * blockDim.x + threadIdx.x) >> 5;
    int lane = threadIdx.x & 31;
    if (warp >= n) return;

    const int t = lane * 4;
    const int start = g_off[warp];
    const int end   = g_cur[warp];

    const float4 q = *(const float4*)(g_Q + (size_t)warp * 128 + t);

    float ax = 0.f, ay = 0.f, az = 0.f, aw = 0.f;
    float den = 0.f;

    int i = start;
    for (; i + 1 < end; i += 2) {
        int s0 = g_esrc[i];
        int s1 = g_esrc[i + 1];
        uint4 kv0 = *(const uint4*)(g_KV + (size_t)s0 * 256 + lane * 8);
        uint4 kv1 = *(const uint4*)(g_KV + (size_t)s1 * 256 + lane * 8);

        float2 k01 = __half22float2(*(__half2*)&kv0.x);
        float2 k23 = __half22float2(*(__half2*)&kv0.y);
        float p0 = q.x * k01.x + q.y * k01.y + q.z * k23.x + q.w * k23.y;
        float2 l01 = __half22float2(*(__half2*)&kv1.x);
        float2 l23 = __half22float2(*(__half2*)&kv1.y);
        float p1 = q.x * l01.x + q.y * l01.y + q.z * l23.x + q.w * l23.y;

        p0 += __shfl_xor_sync(0xFFFFFFFFu, p0, 1);
        p1 += __shfl_xor_sync(0xFFFFFFFFu, p1, 1);
        p0 += __shfl_xor_sync(0xFFFFFFFFu, p0, 2);
        p1 += __shfl_xor_sync(0xFFFFFFFFu, p1, 2);
        float e0 = __expf(p0 * 0.25f);
        float e1 = __expf(p1 * 0.25f);

        float2 v01 = __half22float2(*(__half2*)&kv0.z);
        float2 v23 = __half22float2(*(__half2*)&kv0.w);
        float2 w01 = __half22float2(*(__half2*)&kv1.z);
        float2 w23 = __half22float2(*(__half2*)&kv1.w);
        ax = fmaf(e0, v01.x, fmaf(e1, w01.x, ax));
        ay = fmaf(e0, v01.y, fmaf(e1, w01.y, ay));
        az = fmaf(e0, v23.x, fmaf(e1, w23.x, az));
        aw = fmaf(e0, v23.y, fmaf(e1, w23.y, aw));
        den += e0 + e1;
    }
    if (i < end) {
        int s = g_esrc[i];
        uint4 kv = *(const uint4*)(g_KV + (size_t)s * 256 + lane * 8);
        float2 k01 = __half22float2(*(__half2*)&kv.x);
        float2 k23 = __half22float2(*(__half2*)&kv.y);
        float p = q.x * k01.x + q.y * k01.y + q.z * k23.x + q.w * k23.y;
        p += __shfl_xor_sync(0xFFFFFFFFu, p, 1);
        p += __shfl_xor_sync(0xFFFFFFFFu, p, 2);
        float e = __expf(p * 0.25f);
        float2 v01 = __half22float2(*(__half2*)&kv.z);
        float2 v23 = __half22float2(*(__half2*)&kv.w);
        ax = fmaf(e, v01.x, ax);
        ay = fmaf(e, v01.y, ay);
        az = fmaf(e, v23.x, az);
        aw = fmaf(e, v23.y, aw);
        den += e;
    }

    float inv = 1.f / den;
    float4 o;
    o.x = ax * inv; o.y = ay * inv; o.z = az * inv; o.w = aw * inv;
    *(float4*)(out + (size_t)warp * 128 + t) = o;
}

// ---------------- launch ------------------------------------------------
struct ForkResources {
    cudaStream_t s1;
    cudaEvent_t evFork, evJoin;
    ForkResources() {
        cudaStreamCreateWithFlags(&s1, cudaStreamNonBlocking);
        cudaEventCreateWithFlags(&evFork, cudaEventDisableTiming);
        cudaEventCreateWithFlags(&evJoin, cudaEventDisableTiming);
    }
};

extern "C" void kernel_launch(void* const* d_in, const int* in_sizes, int n_in,
                              void* d_out, int out_size)
{
    static ForkResources fork;   // first call, after harness init

    const float* h  = (const float*)d_in[0];
    const float* wq = (const float*)d_in[1];
    const float* bq = (const float*)d_in[2];
    const float* wk = (const float*)d_in[3];
    const float* bk = (const float*)d_in[4];
    const float* wv = (const float*)d_in[5];
    const float* bv = (const float*)d_in[6];
    const int*  src = (const int*)d_in[7];
    const int*  dst = (const int*)d_in[8];

    const int n = in_sizes[0] / HID;
    const int E = in_sizes[7];
    const int nb = (n + SCAN_BLK - 1) / SCAN_BLK;
    const int e4blocks = ((E + 3) / 4 + 255) / 256;

    float* out = (float*)d_out;

    // Fork: CSR build on side stream, GEMM on main stream. Join before gather.
    cudaEventRecord(fork.evFork, 0);
    cudaStreamWaitEvent(fork.s1, fork.evFork, 0);

    hist_kernel<<<e4blocks, 256, 0, fork.s1>>>(dst, E);
    scan_partial<<<nb, SCAN_BLK, 0, fork.s1>>>(n);
    scan_bsums<<<1, SCAN_BLK, 0, fork.s1>>>(nb);
    scan_final<<<nb, SCAN_BLK, 0, fork.s1>>>(n);
    scatter_kernel<<<e4blocks, 256, 0, fork.s1>>>(src, dst, E);
    cudaEventRecord(fork.evJoin, fork.s1);

    {
        dim3 grid((n + 127) / 128, 3);
        qkv_gemm<<<grid, 256>>>(h, wq, bq, wk, bk, wv, bv, n);
    }

    cudaStreamWaitEvent(0, fork.evJoin, 0);
    // one warp per node, 2 warps per block (fine-grained tail scheduling)
    gat_gather<<<(n + 1) / 2, 64>>>(out, n);
}